// round 11
// baseline (speedup 1.0000x reference)
#include <cuda_runtime.h>
#include <cuda_bf16.h>
#include <math.h>
#include <stdint.h>

#define BB 2
#define NS 2048
#define EE 1024
#define HH 16
#define HD 64
#define F3 192
#define MT 4096      // B*N rows
#define NQKV 3072    // H*F3 columns of the QKV projection

// ---------------- scratch (__device__ globals; allocation-free rule) -------
__device__ float g_Q[(size_t)BB*HH*NS*HD];
__device__ float g_K[(size_t)BB*HH*NS*HD];
__device__ float g_V[(size_t)BB*HH*NS*HD];
__device__ __nv_bfloat16 g_xhi[(size_t)MT*EE],    g_xlo[(size_t)MT*EE];
__device__ __nv_bfloat16 g_wqhi[(size_t)NQKV*EE], g_wqlo[(size_t)NQKV*EE];
__device__ __nv_bfloat16 g_wohi[(size_t)EE*EE],   g_wolo[(size_t)EE*EE];
__device__ __nv_bfloat16 g_sahi[(size_t)MT*EE],   g_salo[(size_t)MT*EE];

// ---------------- portable PTX helpers (sm_80-era: OK under compute_103) ---
__device__ __forceinline__ uint32_t smem_u32(const void* p) {
    uint32_t a;
    asm("{ .reg .u64 t; cvta.to.shared.u64 t, %1; cvt.u32.u64 %0, t; }"
        : "=r"(a) : "l"(p));
    return a;
}
__device__ __forceinline__ void cp_async16(uint32_t dst, const void* src) {
    asm volatile("cp.async.ca.shared.global [%0], [%1], 16;"
                 :: "r"(dst), "l"(src) : "memory");
}
__device__ __forceinline__ void cp_commit() {
    asm volatile("cp.async.commit_group;" ::: "memory");
}
__device__ __forceinline__ void cp_wait1() {
    asm volatile("cp.async.wait_group 1;" ::: "memory");
}
__device__ __forceinline__ void cp_wait0() {
    asm volatile("cp.async.wait_group 0;" ::: "memory");
}
__device__ __forceinline__ void ldsm4(uint32_t addr, uint32_t& r0, uint32_t& r1,
                                      uint32_t& r2, uint32_t& r3) {
    asm volatile("ldmatrix.sync.aligned.m8n8.x4.shared.b16 {%0,%1,%2,%3}, [%4];"
                 : "=r"(r0), "=r"(r1), "=r"(r2), "=r"(r3) : "r"(addr));
}
__device__ __forceinline__ void mma16816(float* d, const uint32_t* a,
                                         const uint32_t* b) {
    asm volatile(
        "mma.sync.aligned.m16n8k16.row.col.f32.bf16.bf16.f32 "
        "{%0,%1,%2,%3}, {%4,%5,%6,%7}, {%8,%9}, {%0,%1,%2,%3};"
        : "+f"(d[0]), "+f"(d[1]), "+f"(d[2]), "+f"(d[3])
        : "r"(a[0]), "r"(a[1]), "r"(a[2]), "r"(a[3]), "r"(b[0]), "r"(b[1]));
}

// ---------------- prep kernels ---------------------------------------------
__global__ void convert_x_kernel(const float* __restrict__ x) {
    const int i = blockIdx.x * 256 + threadIdx.x;
    const float v = x[i];
    const __nv_bfloat16 h = __float2bfloat16(v);
    g_xhi[i] = h;
    g_xlo[i] = __float2bfloat16(v - __bfloat162float(h));
}

// Transpose+split: in fp32 [R][C] (batch z) -> out bf16 [C][R].
__global__ void transpose_cvt_kernel(const float* __restrict__ in, int R, int C, int mode) {
    __shared__ float t[32][33];
    const size_t bs = (size_t)R * C;
    const float* inb = in + (size_t)blockIdx.z * bs;
    __nv_bfloat16* ohi = (mode == 0 ? g_wqhi : g_wohi) + (size_t)blockIdx.z * bs;
    __nv_bfloat16* olo = (mode == 0 ? g_wqlo : g_wolo) + (size_t)blockIdx.z * bs;

    const int x = blockIdx.x * 32 + threadIdx.x;
    const int y0 = blockIdx.y * 32;
    #pragma unroll
    for (int i = threadIdx.y; i < 32; i += 8)
        t[i][threadIdx.x] = inb[(size_t)(y0 + i) * C + x];
    __syncthreads();
    const int r = y0 + threadIdx.x;
    const int c0 = blockIdx.x * 32;
    #pragma unroll
    for (int i = threadIdx.y; i < 32; i += 8) {
        const float v = t[threadIdx.x][i];
        const __nv_bfloat16 h = __float2bfloat16(v);
        const size_t o = (size_t)(c0 + i) * R + r;
        ohi[o] = h;
        olo[o] = __float2bfloat16(v - __bfloat162float(h));
    }
}

// ---------------- HMMA bf16 split GEMM --------------------------------------
// C[128x128] tile of A[MT,1024] @ B[Ntot,1024]^T. 3-term bf16 split, fp32 acc.
// A tiles: [M,K] row-major; B tiles: [N,K] row-major -> perfect for row.col.
// Smem chunk (r,c16): off = r*64 + ((c ^ (r&3))<<4). Conflict-free for both
// the cp.async stores and all ldmatrix reads.
// mode 0: A=x, B=Wqkv^T -> scatter +bias into g_K/g_Q/g_V (split order k,q,v).
// mode 1: A=SA, B=Wout^T -> out +bias.
#define TILE_B 8192                 // 128 x 32 bf16
#define STAGE_B (4 * TILE_B)        // Ahi, Alo, Bhi, Blo
#define GEMM_SMEM (2 * STAGE_B)     // double buffer = 64 KB

__global__ __launch_bounds__(256) void gemm_mma_kernel(const float* __restrict__ bias,
                                                       float* __restrict__ out,
                                                       int mode) {
    extern __shared__ char sm[];
    const uint32_t sb = smem_u32(sm);
    const int tid = threadIdx.x;
    const int wid = tid >> 5;
    const int lane = tid & 31;
    const int m0 = blockIdx.y * 128;
    const int n0 = blockIdx.x * 128;
    const int wm = wid & 1;        // 2 warps in M (64 each)
    const int wn = wid >> 1;       // 4 warps in N (32 each)

    const __nv_bfloat16 *Ahi, *Alo, *Bhi, *Blo;
    if (mode == 0) { Ahi = g_xhi;  Alo = g_xlo;  Bhi = g_wqhi; Blo = g_wqlo; }
    else           { Ahi = g_sahi; Alo = g_salo; Bhi = g_wohi; Blo = g_wolo; }

    // per-thread cp.async source/dest strides (4 rows x 4 chunks pattern)
    const int r_ld = tid >> 2;            // 0..63 base row, +64 on second pass
    const int c_ld = tid & 3;             // 16B chunk within 64B row

    float acc[4][4][4];
    #pragma unroll
    for (int t = 0; t < 4; ++t)
        #pragma unroll
        for (int n = 0; n < 4; ++n)
            #pragma unroll
            for (int i = 0; i < 4; ++i) acc[t][n][i] = 0.f;

    auto issue = [&](int ch, int stage) {
        const int k0 = ch * 32;
        const uint32_t sbase = sb + stage * STAGE_B;
        #pragma unroll
        for (int half = 0; half < 2; ++half) {
            const int r = r_ld + half * 64;
            const uint32_t doff = (uint32_t)(r * 64 + ((c_ld ^ (r & 3)) << 4));
            const size_t ga = (size_t)(m0 + r) * EE + k0 + c_ld * 8;
            const size_t gb = (size_t)(n0 + r) * EE + k0 + c_ld * 8;
            cp_async16(sbase + 0 * TILE_B + doff, Ahi + ga);
            cp_async16(sbase + 1 * TILE_B + doff, Alo + ga);
            cp_async16(sbase + 2 * TILE_B + doff, Bhi + gb);
            cp_async16(sbase + 3 * TILE_B + doff, Blo + gb);
        }
    };

    issue(0, 0); cp_commit();
    issue(1, 1); cp_commit();

    for (int ch = 0; ch < 32; ++ch) {
        if (ch < 31) cp_wait1(); else cp_wait0();
        __syncthreads();

        const uint32_t sA = sb + (ch & 1) * STAGE_B;
        const uint32_t sBm = sA + 2 * TILE_B;

        #pragma unroll
        for (int s = 0; s < 2; ++s) {           // two k16 halves of BK=32
            // B fragments: 2 ldsm.x4 per term cover n=32 (4 n8 tiles)
            uint32_t bh[4][2], bl[4][2];
            #pragma unroll
            for (int g = 0; g < 2; ++g) {
                const int row = wn * 32 + g * 16 + (lane & 15);
                const int chk = s * 2 + (lane >> 4);
                const uint32_t off = (uint32_t)(row * 64 + ((chk ^ (row & 3)) << 4));
                uint32_t r0, r1, r2, r3;
                ldsm4(sBm + off, r0, r1, r2, r3);
                bh[2*g+0][0] = r0; bh[2*g+0][1] = r2;
                bh[2*g+1][0] = r1; bh[2*g+1][1] = r3;
                ldsm4(sBm + TILE_B + off, r0, r1, r2, r3);
                bl[2*g+0][0] = r0; bl[2*g+0][1] = r2;
                bl[2*g+1][0] = r1; bl[2*g+1][1] = r3;
            }
            #pragma unroll
            for (int t = 0; t < 4; ++t) {
                const int row = wm * 64 + t * 16 + (lane & 15);
                const int chk = s * 2 + (lane >> 4);
                const uint32_t off = (uint32_t)(row * 64 + ((chk ^ (row & 3)) << 4));
                uint32_t ah[4], al[4];
                ldsm4(sA + off, ah[0], ah[1], ah[2], ah[3]);
                ldsm4(sA + TILE_B + off, al[0], al[1], al[2], al[3]);
                #pragma unroll
                for (int n = 0; n < 4; ++n) {
                    mma16816(acc[t][n], ah, bh[n]);
                    mma16816(acc[t][n], ah, bl[n]);
                    mma16816(acc[t][n], al, bh[n]);
                }
            }
        }
        __syncthreads();
        if (ch + 2 < 32) { issue(ch + 2, ch & 1); cp_commit(); }
    }

    // Epilogue: C fragment -> global (float2 stores, +bias).
    const int rbase = m0 + wm * 64 + (lane >> 2);
    const int cbase = n0 + wn * 32 + (lane & 3) * 2;
    #pragma unroll
    for (int t = 0; t < 4; ++t) {
        #pragma unroll
        for (int n = 0; n < 4; ++n) {
            const int nc = cbase + n * 8;
            const float b0 = bias[nc], b1 = bias[nc + 1];
            #pragma unroll
            for (int hrow = 0; hrow < 2; ++hrow) {
                const int m = rbase + t * 16 + hrow * 8;
                const float v0 = acc[t][n][hrow * 2 + 0] + b0;
                const float v1 = acc[t][n][hrow * 2 + 1] + b1;
                if (mode == 0) {
                    const int hh = nc / F3;
                    const int f  = nc - hh * F3;
                    const int seg = f >> 6;          // 0=K 1=Q 2=V (jnp.split)
                    const int d   = f & 63;
                    float* base = (seg == 0) ? g_K : (seg == 1 ? g_Q : g_V);
                    const int bb = m >> 11, nr = m & (NS - 1);
                    float2* p = (float2*)&base[(((size_t)bb * HH + hh) * NS + nr) * HD + d];
                    *p = make_float2(v0, v1);
                } else {
                    float2* p = (float2*)&out[(size_t)m * EE + nc];
                    *p = make_float2(v0, v1);
                }
            }
        }
    }
}

// ---------------- causal flash attention (fp32 SIMT, unchanged math) --------
__global__ __launch_bounds__(256) void attn_kernel() {
    extern __shared__ float smf[];
    float* Qs  = smf;
    float* KPs = smf + 64 * 64;
    float* Vs  = KPs + 64 * 65;

    const int tid = threadIdx.x;
    const int tx = tid & 15, ty = tid >> 4;
    const int qt = (gridDim.x - 1) - blockIdx.x;
    const int bh = blockIdx.y;
    const float* Qg = g_Q + (size_t)bh * NS * HD;
    const float* Kg = g_K + (size_t)bh * NS * HD;
    const float* Vg = g_V + (size_t)bh * NS * HD;

    #pragma unroll
    for (int it = 0; it < 4; ++it) {
        const int lin = tid + it * 256;
        const int i = lin >> 4, d4 = (lin & 15) * 4;
        *(float4*)&Qs[i * 64 + d4] =
            *(const float4*)(Qg + (size_t)(qt * 64 + i) * HD + d4);
    }

    float m[4], l[4], O[4][4];
    #pragma unroll
    for (int r = 0; r < 4; ++r) {
        m[r] = -1e30f; l[r] = 0.f;
        #pragma unroll
        for (int c = 0; c < 4; ++c) O[r][c] = 0.f;
    }

    for (int kt = 0; kt <= qt; ++kt) {
        __syncthreads();
        #pragma unroll
        for (int it = 0; it < 4; ++it) {
            const int lin = tid + it * 256;
            const int j = lin >> 4, d4 = (lin & 15) * 4;
            const float4 kv = *(const float4*)(Kg + (size_t)(kt * 64 + j) * HD + d4);
            const float4 vv = *(const float4*)(Vg + (size_t)(kt * 64 + j) * HD + d4);
            KPs[j * 65 + d4 + 0] = kv.x; KPs[j * 65 + d4 + 1] = kv.y;
            KPs[j * 65 + d4 + 2] = kv.z; KPs[j * 65 + d4 + 3] = kv.w;
            Vs [j * 65 + d4 + 0] = vv.x; Vs [j * 65 + d4 + 1] = vv.y;
            Vs [j * 65 + d4 + 2] = vv.z; Vs [j * 65 + d4 + 3] = vv.w;
        }
        __syncthreads();

        float s[4][4];
        #pragma unroll
        for (int r = 0; r < 4; ++r)
            #pragma unroll
            for (int c = 0; c < 4; ++c) s[r][c] = 0.f;
        #pragma unroll 8
        for (int d = 0; d < 64; ++d) {
            float a[4], bk[4];
            #pragma unroll
            for (int r = 0; r < 4; ++r) a[r]  = Qs[(ty * 4 + r) * 64 + d];
            #pragma unroll
            for (int c = 0; c < 4; ++c) bk[c] = KPs[(tx * 4 + c) * 65 + d];
            #pragma unroll
            for (int r = 0; r < 4; ++r)
                #pragma unroll
                for (int c = 0; c < 4; ++c) s[r][c] += a[r] * bk[c];
        }

        const bool diag = (kt == qt);
        #pragma unroll
        for (int r = 0; r < 4; ++r)
            #pragma unroll
            for (int c = 0; c < 4; ++c) {
                s[r][c] *= 0.125f;
                if (diag && (tx * 4 + c) > (ty * 4 + r)) s[r][c] = -1e30f;
            }

        float corr[4];
        #pragma unroll
        for (int r = 0; r < 4; ++r) {
            float tm = fmaxf(fmaxf(s[r][0], s[r][1]), fmaxf(s[r][2], s[r][3]));
            #pragma unroll
            for (int off = 8; off >= 1; off >>= 1)
                tm = fmaxf(tm, __shfl_xor_sync(0xffffffffu, tm, off));
            const float mnew = fmaxf(m[r], tm);
            corr[r] = __expf(m[r] - mnew);
            m[r] = mnew;
            float sum = 0.f;
            #pragma unroll
            for (int c = 0; c < 4; ++c) {
                const float p = __expf(s[r][c] - mnew);
                s[r][c] = p;
                sum += p;
            }
            #pragma unroll
            for (int off = 8; off >= 1; off >>= 1)
                sum += __shfl_xor_sync(0xffffffffu, sum, off);
            l[r] = l[r] * corr[r] + sum;
        }
        #pragma unroll
        for (int r = 0; r < 4; ++r)
            #pragma unroll
            for (int c = 0; c < 4; ++c) O[r][c] *= corr[r];

        __syncthreads();
        #pragma unroll
        for (int r = 0; r < 4; ++r)
            #pragma unroll
            for (int c = 0; c < 4; ++c)
                KPs[(ty * 4 + r) * 65 + tx * 4 + c] = s[r][c];
        __syncthreads();

        #pragma unroll 8
        for (int j = 0; j < 64; ++j) {
            float p[4], v[4];
            #pragma unroll
            for (int r = 0; r < 4; ++r) p[r] = KPs[(ty * 4 + r) * 65 + j];
            #pragma unroll
            for (int c = 0; c < 4; ++c) v[c] = Vs[j * 65 + tx * 4 + c];
            #pragma unroll
            for (int r = 0; r < 4; ++r)
                #pragma unroll
                for (int c = 0; c < 4; ++c)
                    O[r][c] += p[r] * v[c];
        }
    }

    // Epilogue -> SA split into bf16 hi/lo for the tensor-core out-proj.
    const int b = bh >> 4, hd = bh & 15;
    #pragma unroll
    for (int r = 0; r < 4; ++r) {
        const float inv = 1.f / l[r];
        const int n = qt * 64 + ty * 4 + r;
        #pragma unroll
        for (int c = 0; c < 4; ++c) {
            const float o = O[r][c] * inv;
            const __nv_bfloat16 oh = __float2bfloat16(o);
            const size_t idx = ((size_t)b * NS + n) * EE + hd * HD + tx * 4 + c;
            g_sahi[idx] = oh;
            g_salo[idx] = __float2bfloat16(o - __bfloat162float(oh));
        }
    }
}

// ---------------------------------------------------------------------------
extern "C" void kernel_launch(void* const* d_in, const int* in_sizes, int n_in,
                              void* d_out, int out_size) {
    const float* x    = (const float*)d_in[0];
    const float* Wqkv = (const float*)d_in[1];
    const float* bqkv = (const float*)d_in[2];
    const float* Wout = (const float*)d_in[3];
    const float* bout = (const float*)d_in[4];
    float* out = (float*)d_out;

    // Prep: bf16 split of x; transpose+split of Wqkv and Wout.
    convert_x_kernel<<<(MT * EE) / 256, 256>>>(x);
    transpose_cvt_kernel<<<dim3(F3 / 32, EE / 32, HH), dim3(32, 8)>>>(Wqkv, EE, F3, 0);
    transpose_cvt_kernel<<<dim3(EE / 32, EE / 32, 1), dim3(32, 8)>>>(Wout, EE, EE, 1);

    // QKV projection on HMMA: 24 x 32 tiles of 128x128.
    cudaFuncSetAttribute(gemm_mma_kernel, cudaFuncAttributeMaxDynamicSharedMemorySize,
                         GEMM_SMEM);
    gemm_mma_kernel<<<dim3(NQKV / 128, MT / 128), 256, GEMM_SMEM>>>(bqkv, nullptr, 0);

    // Flash attention (fp32 SIMT).
    const int attn_smem = (64 * 64 + 2 * 64 * 65) * (int)sizeof(float);
    cudaFuncSetAttribute(attn_kernel, cudaFuncAttributeMaxDynamicSharedMemorySize,
                         attn_smem);
    attn_kernel<<<dim3(NS / 64, BB * HH), 256, attn_smem>>>();

    // Output projection on HMMA: 8 x 32 tiles.
    gemm_mma_kernel<<<dim3(EE / 128, MT / 128), 256, GEMM_SMEM>>>(bout, out, 1);
}

// round 12
// speedup vs baseline: 1.0107x; 1.0107x over previous
#include <cuda_runtime.h>
#include <cuda_bf16.h>
#include <math.h>
#include <stdint.h>

#define BB 2
#define NS 2048
#define EE 1024
#define HH 16
#define HD 64
#define F3 192
#define MT 4096      // B*N rows
#define NQKV 3072    // H*F3 columns of the QKV projection

// ---------------- scratch (__device__ globals; allocation-free rule) -------
__device__ float g_Q[(size_t)BB*HH*NS*HD];
__device__ float g_K[(size_t)BB*HH*NS*HD];
__device__ float g_V[(size_t)BB*HH*NS*HD];
__device__ __nv_bfloat16 g_xhi[(size_t)MT*EE],    g_xlo[(size_t)MT*EE];
__device__ __nv_bfloat16 g_wqhi[(size_t)NQKV*EE], g_wqlo[(size_t)NQKV*EE];
__device__ __nv_bfloat16 g_wohi[(size_t)EE*EE],   g_wolo[(size_t)EE*EE];
__device__ __nv_bfloat16 g_sahi[(size_t)MT*EE],   g_salo[(size_t)MT*EE];

// ---------------- portable PTX helpers (sm_80-era: OK under compute_103) ---
__device__ __forceinline__ uint32_t smem_u32(const void* p) {
    uint32_t a;
    asm("{ .reg .u64 t; cvta.to.shared.u64 t, %1; cvt.u32.u64 %0, t; }"
        : "=r"(a) : "l"(p));
    return a;
}
__device__ __forceinline__ void cp_async16(uint32_t dst, const void* src) {
    asm volatile("cp.async.ca.shared.global [%0], [%1], 16;"
                 :: "r"(dst), "l"(src) : "memory");
}
__device__ __forceinline__ void cp_commit() {
    asm volatile("cp.async.commit_group;" ::: "memory");
}
__device__ __forceinline__ void cp_wait1() {
    asm volatile("cp.async.wait_group 1;" ::: "memory");
}
__device__ __forceinline__ void cp_wait0() {
    asm volatile("cp.async.wait_group 0;" ::: "memory");
}
__device__ __forceinline__ void ldsm4(uint32_t addr, uint32_t& r0, uint32_t& r1,
                                      uint32_t& r2, uint32_t& r3) {
    asm volatile("ldmatrix.sync.aligned.m8n8.x4.shared.b16 {%0,%1,%2,%3}, [%4];"
                 : "=r"(r0), "=r"(r1), "=r"(r2), "=r"(r3) : "r"(addr));
}
__device__ __forceinline__ void mma16816(float* d, const uint32_t* a,
                                         const uint32_t* b) {
    asm volatile(
        "mma.sync.aligned.m16n8k16.row.col.f32.bf16.bf16.f32 "
        "{%0,%1,%2,%3}, {%4,%5,%6,%7}, {%8,%9}, {%0,%1,%2,%3};"
        : "+f"(d[0]), "+f"(d[1]), "+f"(d[2]), "+f"(d[3])
        : "r"(a[0]), "r"(a[1]), "r"(a[2]), "r"(a[3]), "r"(b[0]), "r"(b[1]));
}

// ---------------- prep kernels ---------------------------------------------
__global__ void convert_x_kernel(const float* __restrict__ x) {
    const int i = blockIdx.x * 256 + threadIdx.x;
    const float v = x[i];
    const __nv_bfloat16 h = __float2bfloat16(v);
    g_xhi[i] = h;
    g_xlo[i] = __float2bfloat16(v - __bfloat162float(h));
}

// Transpose+split: in fp32 [R][C] (batch z) -> out bf16 [C][R].
__global__ void transpose_cvt_kernel(const float* __restrict__ in, int R, int C, int mode) {
    __shared__ float t[32][33];
    const size_t bs = (size_t)R * C;
    const float* inb = in + (size_t)blockIdx.z * bs;
    __nv_bfloat16* ohi = (mode == 0 ? g_wqhi : g_wohi) + (size_t)blockIdx.z * bs;
    __nv_bfloat16* olo = (mode == 0 ? g_wqlo : g_wolo) + (size_t)blockIdx.z * bs;

    const int x = blockIdx.x * 32 + threadIdx.x;
    const int y0 = blockIdx.y * 32;
    #pragma unroll
    for (int i = threadIdx.y; i < 32; i += 8)
        t[i][threadIdx.x] = inb[(size_t)(y0 + i) * C + x];
    __syncthreads();
    const int r = y0 + threadIdx.x;
    const int c0 = blockIdx.x * 32;
    #pragma unroll
    for (int i = threadIdx.y; i < 32; i += 8) {
        const float v = t[threadIdx.x][i];
        const __nv_bfloat16 h = __float2bfloat16(v);
        const size_t o = (size_t)(c0 + i) * R + r;
        ohi[o] = h;
        olo[o] = __float2bfloat16(v - __bfloat162float(h));
    }
}

// ---------------- HMMA bf16 split GEMM --------------------------------------
// C[128x128] tile of A[MT,1024] @ B[Ntot,1024]^T. 3-term bf16 split, fp32 acc.
// A tiles: [M,K] row-major; B tiles: [N,K] row-major -> perfect for row.col.
// Smem chunk (r,c16): off = r*64 + ((c ^ (r&3))<<4). Conflict-free for both
// the cp.async stores and all ldmatrix reads.
// mode 0: A=x, B=Wqkv^T -> scatter +bias into g_K/g_Q/g_V (split order k,q,v).
// mode 1: A=SA, B=Wout^T -> out +bias.
#define TILE_B 8192                 // 128 x 32 bf16
#define STAGE_B (4 * TILE_B)        // Ahi, Alo, Bhi, Blo
#define GEMM_SMEM (2 * STAGE_B)     // double buffer = 64 KB

__global__ __launch_bounds__(256) void gemm_mma_kernel(const float* __restrict__ bias,
                                                       float* __restrict__ out,
                                                       int mode) {
    extern __shared__ char sm[];
    const uint32_t sb = smem_u32(sm);
    const int tid = threadIdx.x;
    const int wid = tid >> 5;
    const int lane = tid & 31;
    const int m0 = blockIdx.y * 128;
    const int n0 = blockIdx.x * 128;
    const int wm = wid & 1;        // 2 warps in M (64 each)
    const int wn = wid >> 1;       // 4 warps in N (32 each)

    const __nv_bfloat16 *Ahi, *Alo, *Bhi, *Blo;
    if (mode == 0) { Ahi = g_xhi;  Alo = g_xlo;  Bhi = g_wqhi; Blo = g_wqlo; }
    else           { Ahi = g_sahi; Alo = g_salo; Bhi = g_wohi; Blo = g_wolo; }

    // per-thread cp.async source/dest strides (4 rows x 4 chunks pattern)
    const int r_ld = tid >> 2;            // 0..63 base row, +64 on second pass
    const int c_ld = tid & 3;             // 16B chunk within 64B row

    float acc[4][4][4];
    #pragma unroll
    for (int t = 0; t < 4; ++t)
        #pragma unroll
        for (int n = 0; n < 4; ++n)
            #pragma unroll
            for (int i = 0; i < 4; ++i) acc[t][n][i] = 0.f;

    auto issue = [&](int ch, int stage) {
        const int k0 = ch * 32;
        const uint32_t sbase = sb + stage * STAGE_B;
        #pragma unroll
        for (int half = 0; half < 2; ++half) {
            const int r = r_ld + half * 64;
            const uint32_t doff = (uint32_t)(r * 64 + ((c_ld ^ (r & 3)) << 4));
            const size_t ga = (size_t)(m0 + r) * EE + k0 + c_ld * 8;
            const size_t gb = (size_t)(n0 + r) * EE + k0 + c_ld * 8;
            cp_async16(sbase + 0 * TILE_B + doff, Ahi + ga);
            cp_async16(sbase + 1 * TILE_B + doff, Alo + ga);
            cp_async16(sbase + 2 * TILE_B + doff, Bhi + gb);
            cp_async16(sbase + 3 * TILE_B + doff, Blo + gb);
        }
    };

    issue(0, 0); cp_commit();
    issue(1, 1); cp_commit();

    for (int ch = 0; ch < 32; ++ch) {
        if (ch < 31) cp_wait1(); else cp_wait0();
        __syncthreads();

        const uint32_t sA = sb + (ch & 1) * STAGE_B;
        const uint32_t sBm = sA + 2 * TILE_B;

        #pragma unroll
        for (int s = 0; s < 2; ++s) {           // two k16 halves of BK=32
            // B fragments: 2 ldsm.x4 per term cover n=32 (4 n8 tiles)
            uint32_t bh[4][2], bl[4][2];
            #pragma unroll
            for (int g = 0; g < 2; ++g) {
                const int row = wn * 32 + g * 16 + (lane & 15);
                const int chk = s * 2 + (lane >> 4);
                const uint32_t off = (uint32_t)(row * 64 + ((chk ^ (row & 3)) << 4));
                uint32_t r0, r1, r2, r3;
                ldsm4(sBm + off, r0, r1, r2, r3);
                bh[2*g+0][0] = r0; bh[2*g+0][1] = r2;
                bh[2*g+1][0] = r1; bh[2*g+1][1] = r3;
                ldsm4(sBm + TILE_B + off, r0, r1, r2, r3);
                bl[2*g+0][0] = r0; bl[2*g+0][1] = r2;
                bl[2*g+1][0] = r1; bl[2*g+1][1] = r3;
            }
            #pragma unroll
            for (int t = 0; t < 4; ++t) {
                const int row = wm * 64 + t * 16 + (lane & 15);
                const int chk = s * 2 + (lane >> 4);
                const uint32_t off = (uint32_t)(row * 64 + ((chk ^ (row & 3)) << 4));
                uint32_t ah[4], al[4];
                ldsm4(sA + off, ah[0], ah[1], ah[2], ah[3]);
                ldsm4(sA + TILE_B + off, al[0], al[1], al[2], al[3]);
                #pragma unroll
                for (int n = 0; n < 4; ++n) {
                    mma16816(acc[t][n], ah, bh[n]);
                    mma16816(acc[t][n], ah, bl[n]);
                    mma16816(acc[t][n], al, bh[n]);
                }
            }
        }
        __syncthreads();
        if (ch + 2 < 32) { issue(ch + 2, ch & 1); cp_commit(); }
    }

    // Epilogue: C fragment -> global (float2 stores, +bias).
    const int rbase = m0 + wm * 64 + (lane >> 2);
    const int cbase = n0 + wn * 32 + (lane & 3) * 2;
    #pragma unroll
    for (int t = 0; t < 4; ++t) {
        #pragma unroll
        for (int n = 0; n < 4; ++n) {
            const int nc = cbase + n * 8;
            const float b0 = bias[nc], b1 = bias[nc + 1];
            #pragma unroll
            for (int hrow = 0; hrow < 2; ++hrow) {
                const int m = rbase + t * 16 + hrow * 8;
                const float v0 = acc[t][n][hrow * 2 + 0] + b0;
                const float v1 = acc[t][n][hrow * 2 + 1] + b1;
                if (mode == 0) {
                    const int hh = nc / F3;
                    const int f  = nc - hh * F3;
                    const int seg = f >> 6;          // 0=K 1=Q 2=V (jnp.split)
                    const int d   = f & 63;
                    float* base = (seg == 0) ? g_K : (seg == 1 ? g_Q : g_V);
                    const int bb = m >> 11, nr = m & (NS - 1);
                    float2* p = (float2*)&base[(((size_t)bb * HH + hh) * NS + nr) * HD + d];
                    *p = make_float2(v0, v1);
                } else {
                    float2* p = (float2*)&out[(size_t)m * EE + nc];
                    *p = make_float2(v0, v1);
                }
            }
        }
    }
}

// ---------------- causal flash attention (fp32 SIMT, unchanged math) --------
__global__ __launch_bounds__(256) void attn_kernel() {
    extern __shared__ float smf[];
    float* Qs  = smf;
    float* KPs = smf + 64 * 64;
    float* Vs  = KPs + 64 * 65;

    const int tid = threadIdx.x;
    const int tx = tid & 15, ty = tid >> 4;
    const int qt = (gridDim.x - 1) - blockIdx.x;
    const int bh = blockIdx.y;
    const float* Qg = g_Q + (size_t)bh * NS * HD;
    const float* Kg = g_K + (size_t)bh * NS * HD;
    const float* Vg = g_V + (size_t)bh * NS * HD;

    #pragma unroll
    for (int it = 0; it < 4; ++it) {
        const int lin = tid + it * 256;
        const int i = lin >> 4, d4 = (lin & 15) * 4;
        *(float4*)&Qs[i * 64 + d4] =
            *(const float4*)(Qg + (size_t)(qt * 64 + i) * HD + d4);
    }

    float m[4], l[4], O[4][4];
    #pragma unroll
    for (int r = 0; r < 4; ++r) {
        m[r] = -1e30f; l[r] = 0.f;
        #pragma unroll
        for (int c = 0; c < 4; ++c) O[r][c] = 0.f;
    }

    for (int kt = 0; kt <= qt; ++kt) {
        __syncthreads();
        #pragma unroll
        for (int it = 0; it < 4; ++it) {
            const int lin = tid + it * 256;
            const int j = lin >> 4, d4 = (lin & 15) * 4;
            const float4 kv = *(const float4*)(Kg + (size_t)(kt * 64 + j) * HD + d4);
            const float4 vv = *(const float4*)(Vg + (size_t)(kt * 64 + j) * HD + d4);
            KPs[j * 65 + d4 + 0] = kv.x; KPs[j * 65 + d4 + 1] = kv.y;
            KPs[j * 65 + d4 + 2] = kv.z; KPs[j * 65 + d4 + 3] = kv.w;
            Vs [j * 65 + d4 + 0] = vv.x; Vs [j * 65 + d4 + 1] = vv.y;
            Vs [j * 65 + d4 + 2] = vv.z; Vs [j * 65 + d4 + 3] = vv.w;
        }
        __syncthreads();

        float s[4][4];
        #pragma unroll
        for (int r = 0; r < 4; ++r)
            #pragma unroll
            for (int c = 0; c < 4; ++c) s[r][c] = 0.f;
        #pragma unroll 8
        for (int d = 0; d < 64; ++d) {
            float a[4], bk[4];
            #pragma unroll
            for (int r = 0; r < 4; ++r) a[r]  = Qs[(ty * 4 + r) * 64 + d];
            #pragma unroll
            for (int c = 0; c < 4; ++c) bk[c] = KPs[(tx * 4 + c) * 65 + d];
            #pragma unroll
            for (int r = 0; r < 4; ++r)
                #pragma unroll
                for (int c = 0; c < 4; ++c) s[r][c] += a[r] * bk[c];
        }

        const bool diag = (kt == qt);
        #pragma unroll
        for (int r = 0; r < 4; ++r)
            #pragma unroll
            for (int c = 0; c < 4; ++c) {
                s[r][c] *= 0.125f;
                if (diag && (tx * 4 + c) > (ty * 4 + r)) s[r][c] = -1e30f;
            }

        float corr[4];
        #pragma unroll
        for (int r = 0; r < 4; ++r) {
            float tm = fmaxf(fmaxf(s[r][0], s[r][1]), fmaxf(s[r][2], s[r][3]));
            #pragma unroll
            for (int off = 8; off >= 1; off >>= 1)
                tm = fmaxf(tm, __shfl_xor_sync(0xffffffffu, tm, off));
            const float mnew = fmaxf(m[r], tm);
            corr[r] = __expf(m[r] - mnew);
            m[r] = mnew;
            float sum = 0.f;
            #pragma unroll
            for (int c = 0; c < 4; ++c) {
                const float p = __expf(s[r][c] - mnew);
                s[r][c] = p;
                sum += p;
            }
            #pragma unroll
            for (int off = 8; off >= 1; off >>= 1)
                sum += __shfl_xor_sync(0xffffffffu, sum, off);
            l[r] = l[r] * corr[r] + sum;
        }
        #pragma unroll
        for (int r = 0; r < 4; ++r)
            #pragma unroll
            for (int c = 0; c < 4; ++c) O[r][c] *= corr[r];

        __syncthreads();
        #pragma unroll
        for (int r = 0; r < 4; ++r)
            #pragma unroll
            for (int c = 0; c < 4; ++c)
                KPs[(ty * 4 + r) * 65 + tx * 4 + c] = s[r][c];
        __syncthreads();

        #pragma unroll 8
        for (int j = 0; j < 64; ++j) {
            float p[4], v[4];
            #pragma unroll
            for (int r = 0; r < 4; ++r) p[r] = KPs[(ty * 4 + r) * 65 + j];
            #pragma unroll
            for (int c = 0; c < 4; ++c) v[c] = Vs[j * 65 + tx * 4 + c];
            #pragma unroll
            for (int r = 0; r < 4; ++r)
                #pragma unroll
                for (int c = 0; c < 4; ++c)
                    O[r][c] += p[r] * v[c];
        }
    }

    // Epilogue -> SA split into bf16 hi/lo for the tensor-core out-proj.
    const int b = bh >> 4, hd = bh & 15;
    #pragma unroll
    for (int r = 0; r < 4; ++r) {
        const float inv = 1.f / l[r];
        const int n = qt * 64 + ty * 4 + r;
        #pragma unroll
        for (int c = 0; c < 4; ++c) {
            const float o = O[r][c] * inv;
            const __nv_bfloat16 oh = __float2bfloat16(o);
            const size_t idx = ((size_t)b * NS + n) * EE + hd * HD + tx * 4 + c;
            g_sahi[idx] = oh;
            g_salo[idx] = __float2bfloat16(o - __bfloat162float(oh));
        }
    }
}

// ---------------------------------------------------------------------------
extern "C" void kernel_launch(void* const* d_in, const int* in_sizes, int n_in,
                              void* d_out, int out_size) {
    const float* x    = (const float*)d_in[0];
    const float* Wqkv = (const float*)d_in[1];
    const float* bqkv = (const float*)d_in[2];
    const float* Wout = (const float*)d_in[3];
    const float* bout = (const float*)d_in[4];
    float* out = (float*)d_out;

    // Prep: bf16 split of x; transpose+split of Wqkv and Wout.
    convert_x_kernel<<<(MT * EE) / 256, 256>>>(x);
    transpose_cvt_kernel<<<dim3(F3 / 32, EE / 32, HH), dim3(32, 8)>>>(Wqkv, EE, F3, 0);
    transpose_cvt_kernel<<<dim3(EE / 32, EE / 32, 1), dim3(32, 8)>>>(Wout, EE, EE, 1);

    // QKV projection on HMMA: 24 x 32 tiles of 128x128.
    cudaFuncSetAttribute(gemm_mma_kernel, cudaFuncAttributeMaxDynamicSharedMemorySize,
                         GEMM_SMEM);
    gemm_mma_kernel<<<dim3(NQKV / 128, MT / 128), 256, GEMM_SMEM>>>(bqkv, nullptr, 0);

    // Flash attention (fp32 SIMT).
    const int attn_smem = (64 * 64 + 2 * 64 * 65) * (int)sizeof(float);
    cudaFuncSetAttribute(attn_kernel, cudaFuncAttributeMaxDynamicSharedMemorySize,
                         attn_smem);
    attn_kernel<<<dim3(NS / 64, BB * HH), 256, attn_smem>>>();

    // Output projection on HMMA: 8 x 32 tiles.
    gemm_mma_kernel<<<dim3(EE / 128, MT / 128), 256, GEMM_SMEM>>>(bout, out, 1);
}